// round 14
// baseline (speedup 1.0000x reference)
#include <cuda_runtime.h>
#include <float.h>
#include <math.h>
#include <stdint.h>

// ---------------- problem constants ----------------
#define HIDDEN   2048
#define N_HEADS  16
#define QK_NOPE  128
#define QK_ROPE  64
#define V_DIM    128
#define Q_LORA   1536
#define KV_LORA  512
#define QK_HEAD  192
#define T_MAX    4096
#define NC       2112   // Q_LORA + KV_LORA + QK_ROPE

// ---------------- scratch ----------------
__device__ float g_hid  [T_MAX * HIDDEN];
__device__ float g_wct  [NC * HIDDEN];
__device__ float g_wqbt [3072 * Q_LORA];
__device__ float g_wkvbt[4096 * KV_LORA];
__device__ float g_wot  [HIDDEN * HIDDEN];
__device__ float g_qkva [T_MAX * NC];
__device__ float g_kvn  [T_MAX * KV_LORA];
__device__ float g_kv   [T_MAX * N_HEADS * (QK_NOPE + V_DIM)];
__device__ float g_q    [T_MAX * N_HEADS * QK_HEAD];
__device__ float g_kf   [T_MAX * N_HEADS * QK_HEAD];
__device__ float g_vt   [N_HEADS * V_DIM * T_MAX];
__device__ float g_at   [T_MAX * N_HEADS * V_DIM];

// ---------------- helpers ----------------
__device__ __forceinline__ uint32_t f2tf(float f) {
    uint32_t u;
    asm("cvt.rna.tf32.f32 %0, %1;" : "=r"(u) : "f"(f));
    return u;
}
__device__ __forceinline__ float f2tff(float f) { return __uint_as_float(f2tf(f)); }

__device__ __forceinline__ float ex2(float x) {
    float y;
    asm("ex2.approx.ftz.f32 %0, %1;" : "=f"(y) : "f"(x));
    return y;
}

__device__ __forceinline__ void mma8(float* c, const uint32_t* a, const uint32_t* b) {
    asm volatile(
        "mma.sync.aligned.m16n8k8.row.col.f32.tf32.tf32.f32 "
        "{%0,%1,%2,%3}, {%4,%5,%6,%7}, {%8,%9}, {%0,%1,%2,%3};\n"
        : "+f"(c[0]), "+f"(c[1]), "+f"(c[2]), "+f"(c[3])
        : "r"(a[0]), "r"(a[1]), "r"(a[2]), "r"(a[3]), "r"(b[0]), "r"(b[1]));
}

__device__ __forceinline__ void ldsm4(uint32_t& r0, uint32_t& r1, uint32_t& r2,
                                      uint32_t& r3, uint32_t addr) {
    asm volatile("ldmatrix.sync.aligned.m8n8.x4.shared.b16 {%0,%1,%2,%3}, [%4];\n"
                 : "=r"(r0), "=r"(r1), "=r"(r2), "=r"(r3) : "r"(addr));
}

__device__ __forceinline__ void cpa16(uint32_t dst, const void* src, bool valid) {
    int sz = valid ? 16 : 0;
    asm volatile("cp.async.cg.shared.global [%0], [%1], 16, %2;\n"
                 :: "r"(dst), "l"(src), "r"(sz));
}
#define CP_COMMIT() asm volatile("cp.async.commit_group;\n")
#define CP_WAIT1()  asm volatile("cp.async.wait_group 1;\n")
#define CP_WAIT0()  asm volatile("cp.async.wait_group 0;\n")

#define BM 128
#define BN 128
#define BK 32
#define AP 36

#define NT_A_WORDS (BM * AP)
#define NT_STG_WORDS (2 * NT_A_WORDS)
#define NT_SMEM_BYTES (3 * NT_STG_WORDS * 4)

// ---------------- fused prep ----------------
#define PREP_RB     8192
#define PREP_WQA    (PREP_RB + 3072)
#define PREP_WKVA   (PREP_WQA + 1152)
#define PREP_WQB    (PREP_WKVA + 4608)
#define PREP_WKVB   (PREP_WQB + 2048)
#define PREP_TOTAL  (PREP_WKVB + 4096)

__device__ __forceinline__ void tr_tile(const float* __restrict__ in,
                                        float* __restrict__ out,
                                        int ldin, int ldout, int bx, int by,
                                        float (*t)[33])
{
    const int k0 = by * 32, n0 = bx * 32;
    const int tx = threadIdx.x & 31, ty = threadIdx.x >> 5;
    #pragma unroll
    for (int r = 0; r < 32; r += 8)
        t[ty + r][tx] = in[(long long)(k0 + ty + r) * ldin + n0 + tx];
    __syncthreads();
    #pragma unroll
    for (int r = 0; r < 32; r += 8)
        out[(long long)(n0 + ty + r) * ldout + k0 + tx] = f2tff(t[tx][ty + r]);
}

__global__ __launch_bounds__(256)
void prep_all(const float4* __restrict__ hidden4, float4* __restrict__ hid4,
              const float* __restrict__ Wqa, const float* __restrict__ Wkva,
              const float* __restrict__ Wqb, const float* __restrict__ Wkvb,
              const float* __restrict__ Wo,
              float* __restrict__ wct, float* __restrict__ wqbt,
              float* __restrict__ wkvbt, float* __restrict__ wot)
{
    __shared__ float t[32][33];
    int b = blockIdx.x;
    if (b < PREP_RB) {
        int i = b * 256 + threadIdx.x;
        float4 v = hidden4[i];
        v.x = f2tff(v.x); v.y = f2tff(v.y); v.z = f2tff(v.z); v.w = f2tff(v.w);
        hid4[i] = v;
    } else if (b < PREP_WQA) {
        int idx = b - PREP_RB;
        tr_tile(Wqa, wct, Q_LORA, HIDDEN, idx % 48, idx / 48, t);
    } else if (b < PREP_WKVA) {
        int idx = b - PREP_WQA;
        tr_tile(Wkva, wct + (long long)Q_LORA * HIDDEN, NC - Q_LORA, HIDDEN,
                idx % 18, idx / 18, t);
    } else if (b < PREP_WQB) {
        int idx = b - PREP_WKVA;
        tr_tile(Wqb, wqbt, 3072, Q_LORA, idx % 96, idx / 96, t);
    } else if (b < PREP_WKVB) {
        int idx = b - PREP_WQB;
        tr_tile(Wkvb, wkvbt, 4096, KV_LORA, idx % 128, idx / 128, t);
    } else {
        int idx = b - PREP_WKVB;
        tr_tile(Wo, wot, HIDDEN, HIDDEN, idx % 64, idx / 64, t);
    }
}

// ---------------- C = alpha * A(MxK) @ B^T; A,B k-major, BOTH tf32 ---------
__global__ __launch_bounds__(256, 2)
void mm_nt(const float* __restrict__ A, const float* __restrict__ B,
           float* __restrict__ C,
           int M, int N, int K, int lda, int ldb, int ldc,
           float alpha, int store_tf32)
{
    extern __shared__ float smem[];
    const uint32_t sbase = (uint32_t)__cvta_generic_to_shared(smem);

    const int bm = blockIdx.y * BM, bn = blockIdx.x * BN;

    const int tid  = threadIdx.x;
    const int lane = tid & 31, wid = tid >> 5;
    const int wm = (wid & 1) * 64, wn = (wid >> 1) * 32;
    const int lr = lane >> 2, lc = lane & 3;

    const int iters = K / BK;

    float acc[4][4][4] = {};

    auto load_stage = [&](int s, int k0) {
        uint32_t sa = sbase + (uint32_t)(s * NT_STG_WORDS) * 4u;
        uint32_t sb = sa + NT_A_WORDS * 4u;
        #pragma unroll
        for (int i = 0; i < 4; i++) {
            int ch = tid + i * 256;
            int row = ch >> 3, kc = (ch & 7) * 4;
            cpa16(sa + (uint32_t)(row * AP + kc) * 4u,
                  A + (long long)(bm + row) * lda + k0 + kc, true);
        }
        #pragma unroll
        for (int i = 0; i < 4; i++) {
            int ch = tid + i * 256;
            int row = ch >> 3, kc = (ch & 7) * 4;
            cpa16(sb + (uint32_t)(row * AP + kc) * 4u,
                  B + (long long)(bn + row) * ldb + k0 + kc, (bn + row) < N);
        }
    };

    load_stage(0, 0);
    CP_COMMIT();

    const int arow  = (lane & 7) + ((lane >> 3) & 1) * 8;
    const int akoff = (lane >> 4) * 4;
    const int brow  = (lane & 7) + (lane >> 4) * 8;
    const int bkoff = ((lane >> 3) & 1) * 4;

    for (int it = 0; it < iters; it++) {
        const int s = it % 3;
        if (it + 1 < iters) {
            load_stage((it + 1) % 3, (it + 1) * BK);
            CP_COMMIT();
            CP_WAIT1();
        } else {
            CP_WAIT0();
        }
        __syncthreads();

        uint32_t sa = sbase + (uint32_t)(s * NT_STG_WORDS) * 4u;
        uint32_t sb = sa + NT_A_WORDS * 4u;

        #pragma unroll
        for (int ks = 0; ks < BK; ks += 8) {
            uint32_t af[4][4], bf[4][2];
            #pragma unroll
            for (int mt = 0; mt < 4; mt++) {
                uint32_t addr = sa + (uint32_t)((wm + mt * 16 + arow) * AP + ks + akoff) * 4u;
                ldsm4(af[mt][0], af[mt][1], af[mt][2], af[mt][3], addr);
            }
            #pragma unroll
            for (int nt = 0; nt < 4; nt += 2) {
                uint32_t addr = sb + (uint32_t)((wn + nt * 8 + brow) * AP + ks + bkoff) * 4u;
                ldsm4(bf[nt][0], bf[nt][1], bf[nt + 1][0], bf[nt + 1][1], addr);
            }
            #pragma unroll
            for (int mt = 0; mt < 4; mt++)
                #pragma unroll
                for (int nt = 0; nt < 4; nt++)
                    mma8(acc[mt][nt], af[mt], bf[nt]);
        }
    }

    #pragma unroll
    for (int mt = 0; mt < 4; mt++) {
        int r0 = bm + wm + mt * 16 + lr;
        #pragma unroll
        for (int nt = 0; nt < 4; nt++) {
            int c = bn + wn + nt * 8 + 2 * lc;
            if (c < N) {
                float v00 = alpha * acc[mt][nt][0], v01 = alpha * acc[mt][nt][1];
                float v10 = alpha * acc[mt][nt][2], v11 = alpha * acc[mt][nt][3];
                if (store_tf32) {
                    v00 = f2tff(v00); v01 = f2tff(v01);
                    v10 = f2tff(v10); v11 = f2tff(v11);
                }
                C[(long long)r0 * ldc + c]           = v00;
                C[(long long)r0 * ldc + c + 1]       = v01;
                C[(long long)(r0 + 8) * ldc + c]     = v10;
                C[(long long)(r0 + 8) * ldc + c + 1] = v11;
            }
        }
    }
}

// ---------------- RMSNorm (tf32 out) ----------------
__global__ __launch_bounds__(256)
void rmsnorm_k(const float* __restrict__ in, const float* __restrict__ w,
               float* __restrict__ out, int n, int ld_in, int ld_out)
{
    const int t = blockIdx.x;
    const float* x = in + (long long)t * ld_in;
    float* o = out + (long long)t * ld_out;

    float s = 0.f;
    for (int i = threadIdx.x; i < n; i += blockDim.x) {
        float v = x[i];
        s += v * v;
    }
    __shared__ float red[8];
    __shared__ float tot;
    #pragma unroll
    for (int off = 16; off; off >>= 1) s += __shfl_xor_sync(0xffffffffu, s, off);
    if ((threadIdx.x & 31) == 0) red[threadIdx.x >> 5] = s;
    __syncthreads();
    if (threadIdx.x < 32) {
        float v = (threadIdx.x < 8) ? red[threadIdx.x] : 0.f;
        #pragma unroll
        for (int off = 4; off; off >>= 1) v += __shfl_xor_sync(0xffffffffu, v, off);
        if (threadIdx.x == 0) tot = v;
    }
    __syncthreads();
    float scale = 1.0f / sqrtf(tot / (float)n + 1e-6f);
    for (int i = threadIdx.x; i < n; i += blockDim.x)
        o[i] = f2tff(x[i] * scale * w[i]);
}

// ---------------- RoPE: q in place + kf assembly ----------------
__global__ __launch_bounds__(256)
void rope_assemble(float* __restrict__ q, const float* __restrict__ kv,
                   const float* __restrict__ qkva, float* __restrict__ kf, int T)
{
    const int t = blockIdx.x;
    __shared__ float cs[32], sn[32];
    if (threadIdx.x < 32) {
        double fr = (double)t * pow(10000.0, -(double)threadIdx.x / 32.0);
        cs[threadIdx.x] = (float)cos(fr);
        sn[threadIdx.x] = (float)sin(fr);
    }
    __syncthreads();

    for (int i = threadIdx.x; i < N_HEADS * QK_NOPE; i += blockDim.x) {
        int h = i >> 7, d = i & 127;
        kf[(long long)t * 3072 + h * QK_HEAD + d] = kv[(long long)t * 4096 + h * 256 + d];
    }
    for (int i = threadIdx.x; i < N_HEADS * 32; i += blockDim.x) {
        int h = i >> 5, p = i & 31;
        float c = cs[p], s = sn[p];

        long long qoff = (long long)t * 3072 + h * QK_HEAD + QK_NOPE + 2 * p;
        float x1 = q[qoff], x2 = q[qoff + 1];
        q[qoff]     = f2tff(x1 * c - x2 * s);
        q[qoff + 1] = f2tff(x2 * c + x1 * s);

        long long koff = (long long)t * NC + (Q_LORA + KV_LORA) + 2 * p;
        float k1 = qkva[koff], k2 = qkva[koff + 1];
        long long foff = (long long)t * 3072 + h * QK_HEAD + QK_NOPE + 2 * p;
        kf[foff]     = f2tff(k1 * c - k2 * s);
        kf[foff + 1] = f2tff(k2 * c + k1 * s);
    }
}

// ---------------- V transpose ----------------
__global__ __launch_bounds__(256)
void transpose_v(const float* __restrict__ kv, float* __restrict__ vt, int T)
{
    __shared__ float tile[32][129];
    const int t0 = blockIdx.x * 32, h = blockIdx.y;
    #pragma unroll
    for (int c = 0; c < 16; c++) {
        int idx = threadIdx.x + c * 256;
        int tt = idx >> 7, vd = idx & 127;
        tile[tt][vd] = kv[(long long)(t0 + tt) * 4096 + h * 256 + 128 + vd];
    }
    __syncthreads();
    #pragma unroll
    for (int c = 0; c < 16; c++) {
        int idx = threadIdx.x + c * 256;
        int vd = idx >> 5, tt = idx & 31;
        vt[(long long)h * (V_DIM * T_MAX) + (long long)vd * T_MAX + t0 + tt] = tile[tt][vd];
    }
}

// ---------------- fused flash attention: 64-key tiles, Q in regs -----------
// smem layout (words): K0=0 (64x196), K1=12544, V0=25088 (128x68),
// V1=33792, P=42496 (128x68). total 51200 words = 204800 B.
// Q (128x196) is loaded at offset 0 in the prologue and consumed into
// registers before the K ring starts overwriting it.
#define QP 196
#define VP 68
#define PP 68
#define K_STG 12544
#define V_OFF 25088
#define V_STG 8704
#define P_OFF 42496
#define FL_SMEM_WORDS 51200
#define FL_SMEM_BYTES (FL_SMEM_WORDS * 4)   // 204800

__global__ __launch_bounds__(256, 1)
void flash_attn(const float* __restrict__ qf, const float* __restrict__ kf,
                const float* __restrict__ vt, float* __restrict__ at, int T)
{
    extern __shared__ float smem[];
    const uint32_t sbase = (uint32_t)__cvta_generic_to_shared(smem);

    const int i = (int)gridDim.x - 1 - (int)blockIdx.x;   // heavy blocks first
    const int h = blockIdx.y;
    const int tid  = threadIdx.x;
    const int lane = tid & 31, wid = tid >> 5;
    const int wrb  = wid * 16;
    const int lr = lane >> 2, lc = lane & 3;
    const int gr0 = i * 128 + wrb;

    const int arow  = (lane & 7) + ((lane >> 3) & 1) * 8;
    const int akoff = (lane >> 4) * 4;
    const int brow  = (lane & 7) + (lane >> 4) * 8;
    const int bkoff = ((lane >> 3) & 1) * 4;

    const int NT = 2 * (i + 1);          // 64-key tiles
    const float cexp = 0.07216878364870322f * 1.4426950408889634f;

    // --- prologue: stage Q at offset 0, hoist into registers ---
    #pragma unroll
    for (int c = 0; c < 24; c++) {
        int ch = tid + c * 256;
        int row = ch / 48, c4 = (ch % 48) * 4;
        cpa16(sbase + (uint32_t)(row * QP + c4) * 4u,
              qf + (long long)(i * 128 + row) * 3072 + h * QK_HEAD + c4, true);
    }
    CP_COMMIT();
    CP_WAIT0();
    __syncthreads();

    uint32_t qreg[24][4];
    #pragma unroll
    for (int ks8 = 0; ks8 < 24; ks8++)
        ldsm4(qreg[ks8][0], qreg[ks8][1], qreg[ks8][2], qreg[ks8][3],
              sbase + (uint32_t)((wrb + arow) * QP + ks8 * 8 + akoff) * 4u);
    __syncthreads();   // Q fully consumed; region becomes the K ring

    auto load_kv = [&](int s, int j) {
        uint32_t skb = sbase + (uint32_t)(s * K_STG) * 4u;
        #pragma unroll
        for (int c = 0; c < 12; c++) {          // K: 64 rows x 192 floats
            int ch = tid + c * 256;
            int row = ch / 48, c4 = (ch % 48) * 4;
            cpa16(skb + (uint32_t)(row * QP + c4) * 4u,
                  kf + (long long)(j * 64 + row) * 3072 + h * QK_HEAD + c4, true);
        }
        uint32_t svb = sbase + (uint32_t)(V_OFF + s * V_STG) * 4u;
        #pragma unroll
        for (int c = 0; c < 8; c++) {           // V: 128 vd x 64 keys
            int ch = tid + c * 256;
            int row = ch >> 4, c4 = (ch & 15) * 4;
            cpa16(svb + (uint32_t)(row * VP + c4) * 4u,
                  vt + (long long)h * (V_DIM * T_MAX) + (long long)row * T_MAX + j * 64 + c4,
                  true);
        }
    };

    load_kv(0, 0);
    CP_COMMIT();

    float m0 = -FLT_MAX, m1 = -FLT_MAX, l0 = 0.f, l1 = 0.f;
    float oa[16][4];
    #pragma unroll
    for (int nt = 0; nt < 16; nt++)
        #pragma unroll
        for (int v = 0; v < 4; v++) oa[nt][v] = 0.f;

    const uint32_t spb = sbase + (uint32_t)P_OFF * 4u;

    for (int j = 0; j < NT; j++) {
        const int s = j & 1;
        if (j + 1 < NT) {
            load_kv((j + 1) & 1, j + 1);
            CP_COMMIT();
            CP_WAIT1();
        } else {
            CP_WAIT0();
        }
        __syncthreads();

        // --- S = Q @ K^T : warp computes 16 x 64 ---
        const uint32_t skb = sbase + (uint32_t)(s * K_STG) * 4u;
        float sc[8][4];
        #pragma unroll
        for (int nt = 0; nt < 8; nt++)
            #pragma unroll
            for (int v = 0; v < 4; v++) sc[nt][v] = 0.f;

        #pragma unroll
        for (int ks8 = 0; ks8 < 24; ks8++) {
            uint32_t b[8][2];
            ldsm4(b[0][0], b[0][1], b[1][0], b[1][1],
                  skb + (uint32_t)(brow * QP + ks8 * 8 + bkoff) * 4u);
            ldsm4(b[2][0], b[2][1], b[3][0], b[3][1],
                  skb + (uint32_t)((16 + brow) * QP + ks8 * 8 + bkoff) * 4u);
            ldsm4(b[4][0], b[4][1], b[5][0], b[5][1],
                  skb + (uint32_t)((32 + brow) * QP + ks8 * 8 + bkoff) * 4u);
            ldsm4(b[6][0], b[6][1], b[7][0], b[7][1],
                  skb + (uint32_t)((48 + brow) * QP + ks8 * 8 + bkoff) * 4u);
            #pragma unroll
            for (int nt = 0; nt < 8; nt++) mma8(sc[nt], qreg[ks8], b[nt]);
        }

        // --- causal mask (raw scores) ---
        if (j >= 2 * i) {
            #pragma unroll
            for (int nt = 0; nt < 8; nt++)
                #pragma unroll
                for (int v = 0; v < 4; v++) {
                    int kg = j * 64 + nt * 8 + 2 * lc + (v & 1);
                    int rr = gr0 + lr + ((v >> 1) ? 8 : 0);
                    if (kg > rr) sc[nt][v] = -FLT_MAX;
                }
        }

        // --- online softmax (base 2), once per 64 keys ---
        float mx0 = -FLT_MAX, mx1 = -FLT_MAX;
        #pragma unroll
        for (int nt = 0; nt < 8; nt++) {
            mx0 = fmaxf(mx0, fmaxf(sc[nt][0], sc[nt][1]));
            mx1 = fmaxf(mx1, fmaxf(sc[nt][2], sc[nt][3]));
        }
        mx0 = fmaxf(mx0, __shfl_xor_sync(0xffffffffu, mx0, 1));
        mx0 = fmaxf(mx0, __shfl_xor_sync(0xffffffffu, mx0, 2));
        mx1 = fmaxf(mx1, __shfl_xor_sync(0xffffffffu, mx1, 1));
        mx1 = fmaxf(mx1, __shfl_xor_sync(0xffffffffu, mx1, 2));

        float mn0 = fmaxf(m0, mx0), mn1 = fmaxf(m1, mx1);
        float c0 = ex2(cexp * (m0 - mn0)), c1 = ex2(cexp * (m1 - mn1));
        float mc0 = cexp * mn0, mc1 = cexp * mn1;

        float sum0 = 0.f, sum1 = 0.f;
        #pragma unroll
        for (int nt = 0; nt < 8; nt++) {
            float p00 = ex2(fmaf(sc[nt][0], cexp, -mc0));
            float p01 = ex2(fmaf(sc[nt][1], cexp, -mc0));
            float p10 = ex2(fmaf(sc[nt][2], cexp, -mc1));
            float p11 = ex2(fmaf(sc[nt][3], cexp, -mc1));
            sum0 += p00 + p01; sum1 += p10 + p11;
            float* pr0 = smem + P_OFF + (wrb + lr) * PP + nt * 8 + 2 * lc;
            float* pr1 = smem + P_OFF + (wrb + lr + 8) * PP + nt * 8 + 2 * lc;
            pr0[0] = f2tff(p00); pr0[1] = f2tff(p01);
            pr1[0] = f2tff(p10); pr1[1] = f2tff(p11);
        }
        sum0 += __shfl_xor_sync(0xffffffffu, sum0, 1);
        sum0 += __shfl_xor_sync(0xffffffffu, sum0, 2);
        sum1 += __shfl_xor_sync(0xffffffffu, sum1, 1);
        sum1 += __shfl_xor_sync(0xffffffffu, sum1, 2);

        l0 = l0 * c0 + sum0; l1 = l1 * c1 + sum1;
        m0 = mn0; m1 = mn1;

        #pragma unroll
        for (int nt = 0; nt < 16; nt++) {
            oa[nt][0] *= c0; oa[nt][1] *= c0;
            oa[nt][2] *= c1; oa[nt][3] *= c1;
        }
        __syncwarp();

        // --- O += P @ V (P: 16x64, V^T: 128 vd x 64 k) ---
        const uint32_t svb = sbase + (uint32_t)(V_OFF + s * V_STG) * 4u;
        #pragma unroll
        for (int ks = 0; ks < 64; ks += 8) {
            uint32_t a[4];
            ldsm4(a[0], a[1], a[2], a[3],
                  spb + (uint32_t)((wrb + arow) * PP + ks + akoff) * 4u);
            #pragma unroll
            for (int n2 = 0; n2 < 8; n2++) {
                uint32_t b[2][2];
                ldsm4(b[0][0], b[0][1], b[1][0], b[1][1],
                      svb + (uint32_t)((n2 * 16 + brow) * VP + ks + bkoff) * 4u);
                mma8(oa[2 * n2], a, b[0]);
                mma8(oa[2 * n2 + 1], a, b[1]);
            }
        }
        __syncthreads();
    }

    float inv0 = 1.0f / l0, inv1 = 1.0f / l1;
    const long long r0 = (long long)(gr0 + lr) * 2048;
    const long long r1 = (long long)(gr0 + lr + 8) * 2048;
    #pragma unroll
    for (int nt = 0; nt < 16; nt++) {
        int col = h * V_DIM + nt * 8 + 2 * lc;
        at[r0 + col]     = f2tff(oa[nt][0] * inv0);
        at[r0 + col + 1] = f2tff(oa[nt][1] * inv0);
        at[r1 + col]     = f2tff(oa[nt][2] * inv1);
        at[r1 + col + 1] = f2tff(oa[nt][3] * inv1);
    }
}

// ---------------- launch ----------------
extern "C" void kernel_launch(void* const* d_in, const int* in_sizes, int n_in,
                              void* d_out, int out_size)
{
    const float* hidden = (const float*)d_in[0];
    const float* Wqa   = (const float*)d_in[2];
    const float* q_ln  = (const float*)d_in[3];
    const float* Wqb   = (const float*)d_in[4];
    const float* Wkva  = (const float*)d_in[5];
    const float* kv_ln = (const float*)d_in[6];
    const float* Wkvb  = (const float*)d_in[7];
    const float* Wo    = (const float*)d_in[8];
    float* out = (float*)d_out;

    const int T = in_sizes[0] / HIDDEN;   // 4096

    static float *hid = nullptr, *wct = nullptr, *wqbt = nullptr,
                 *wkvbt = nullptr, *wot = nullptr, *qkva = nullptr,
                 *kvn = nullptr, *kv = nullptr, *q = nullptr, *kf = nullptr,
                 *vt = nullptr, *at = nullptr;
    if (!hid) {
        cudaGetSymbolAddress((void**)&hid,   g_hid);
        cudaGetSymbolAddress((void**)&wct,   g_wct);
        cudaGetSymbolAddress((void**)&wqbt,  g_wqbt);
        cudaGetSymbolAddress((void**)&wkvbt, g_wkvbt);
        cudaGetSymbolAddress((void**)&wot,   g_wot);
        cudaGetSymbolAddress((void**)&qkva,  g_qkva);
        cudaGetSymbolAddress((void**)&kvn,   g_kvn);
        cudaGetSymbolAddress((void**)&kv,    g_kv);
        cudaGetSymbolAddress((void**)&q,     g_q);
        cudaGetSymbolAddress((void**)&kf,    g_kf);
        cudaGetSymbolAddress((void**)&vt,    g_vt);
        cudaGetSymbolAddress((void**)&at,    g_at);
        cudaFuncSetAttribute(mm_nt, cudaFuncAttributeMaxDynamicSharedMemorySize, NT_SMEM_BYTES);
        cudaFuncSetAttribute(flash_attn, cudaFuncAttributeMaxDynamicSharedMemorySize, FL_SMEM_BYTES);
    }

    const dim3 thr(256);

    // fused prep (1 launch)
    prep_all<<<PREP_TOTAL, thr>>>(
        (const float4*)hidden, (float4*)hid,
        Wqa, Wkva, Wqb, Wkvb, Wo, wct, wqbt, wkvbt, wot);

    // qkva = hid @ Wc^T
    mm_nt<<<dim3((NC + BN - 1) / BN, T / BM), thr, NT_SMEM_BYTES>>>(
        hid, wct, qkva, T, NC, HIDDEN, HIDDEN, HIDDEN, NC, 1.f, 0);
    // rmsnorms (tf32 out)
    rmsnorm_k<<<T, 256>>>(qkva, q_ln, qkva, Q_LORA, NC, NC);
    rmsnorm_k<<<T, 256>>>(qkva + Q_LORA, kv_ln, kvn, KV_LORA, NC, KV_LORA);
    // q = q_latent @ Wqb^T (tf32 out)
    mm_nt<<<dim3(3072 / BN, T / BM), thr, NT_SMEM_BYTES>>>(
        qkva, wqbt, q, T, 3072, Q_LORA, NC, Q_LORA, 3072, 1.f, 1);
    // kv = kvn @ Wkvb^T (tf32 out)
    mm_nt<<<dim3(4096 / BN, T / BM), thr, NT_SMEM_BYTES>>>(
        kvn, wkvbt, kv, T, 4096, KV_LORA, KV_LORA, KV_LORA, 4096, 1.f, 1);
    // rope q in place + build kf
    rope_assemble<<<T, 256>>>(q, kv, qkva, kf, T);
    // V transpose
    transpose_v<<<dim3(T / 32, N_HEADS), thr>>>(kv, vt, T);
    // fused attention (64-key tiles)
    flash_attn<<<dim3(T / 128, N_HEADS), thr, FL_SMEM_BYTES>>>(q, kf, vt, at, T);
    // out = at @ Wo^T
    mm_nt<<<dim3(HIDDEN / BN, T / BM), thr, NT_SMEM_BYTES>>>(
        at, wot, out, T, HIDDEN, HIDDEN, HIDDEN, HIDDEN, HIDDEN, 1.f, 0);
}

// round 15
// speedup vs baseline: 1.0126x; 1.0126x over previous
#include <cuda_runtime.h>
#include <float.h>
#include <math.h>
#include <stdint.h>

// ---------------- problem constants ----------------
#define HIDDEN   2048
#define N_HEADS  16
#define QK_NOPE  128
#define QK_ROPE  64
#define V_DIM    128
#define Q_LORA   1536
#define KV_LORA  512
#define QK_HEAD  192
#define T_MAX    4096
#define NC       2112   // Q_LORA + KV_LORA + QK_ROPE

// ---------------- scratch ----------------
__device__ float g_hid  [T_MAX * HIDDEN];
__device__ float g_wct  [NC * HIDDEN];
__device__ float g_wqbt [3072 * Q_LORA];
__device__ float g_wkvbt[4096 * KV_LORA];
__device__ float g_wot  [HIDDEN * HIDDEN];
__device__ float g_qkva [T_MAX * NC];
__device__ float g_kvn  [T_MAX * KV_LORA];
__device__ float g_kv   [T_MAX * N_HEADS * (QK_NOPE + V_DIM)];
__device__ float g_q    [T_MAX * N_HEADS * QK_HEAD];
__device__ float g_kf   [T_MAX * N_HEADS * QK_HEAD];
__device__ float g_vt   [N_HEADS * V_DIM * T_MAX];
__device__ float g_at   [T_MAX * N_HEADS * V_DIM];

// ---------------- helpers ----------------
__device__ __forceinline__ uint32_t f2tf(float f) {
    uint32_t u;
    asm("cvt.rna.tf32.f32 %0, %1;" : "=r"(u) : "f"(f));
    return u;
}
__device__ __forceinline__ float f2tff(float f) { return __uint_as_float(f2tf(f)); }

__device__ __forceinline__ float ex2(float x) {
    float y;
    asm("ex2.approx.ftz.f32 %0, %1;" : "=f"(y) : "f"(x));
    return y;
}

__device__ __forceinline__ void mma8(float* c, const uint32_t* a, const uint32_t* b) {
    asm volatile(
        "mma.sync.aligned.m16n8k8.row.col.f32.tf32.tf32.f32 "
        "{%0,%1,%2,%3}, {%4,%5,%6,%7}, {%8,%9}, {%0,%1,%2,%3};\n"
        : "+f"(c[0]), "+f"(c[1]), "+f"(c[2]), "+f"(c[3])
        : "r"(a[0]), "r"(a[1]), "r"(a[2]), "r"(a[3]), "r"(b[0]), "r"(b[1]));
}

__device__ __forceinline__ void ldsm4(uint32_t& r0, uint32_t& r1, uint32_t& r2,
                                      uint32_t& r3, uint32_t addr) {
    asm volatile("ldmatrix.sync.aligned.m8n8.x4.shared.b16 {%0,%1,%2,%3}, [%4];\n"
                 : "=r"(r0), "=r"(r1), "=r"(r2), "=r"(r3) : "r"(addr));
}

__device__ __forceinline__ void cpa16(uint32_t dst, const void* src, bool valid) {
    int sz = valid ? 16 : 0;
    asm volatile("cp.async.cg.shared.global [%0], [%1], 16, %2;\n"
                 :: "r"(dst), "l"(src), "r"(sz));
}
#define CP_COMMIT() asm volatile("cp.async.commit_group;\n")
#define CP_WAIT1()  asm volatile("cp.async.wait_group 1;\n")
#define CP_WAIT0()  asm volatile("cp.async.wait_group 0;\n")

#define BM 128
#define BN 128
#define BK 32
#define AP 36

#define NT_A_WORDS (BM * AP)
#define NT_STG_WORDS (2 * NT_A_WORDS)
#define NT_SMEM_BYTES (3 * NT_STG_WORDS * 4)

// ---------------- fused prep ----------------
#define PREP_RB     8192
#define PREP_WQA    (PREP_RB + 3072)
#define PREP_WKVA   (PREP_WQA + 1152)
#define PREP_WQB    (PREP_WKVA + 4608)
#define PREP_WKVB   (PREP_WQB + 2048)
#define PREP_TOTAL  (PREP_WKVB + 4096)

__device__ __forceinline__ void tr_tile(const float* __restrict__ in,
                                        float* __restrict__ out,
                                        int ldin, int ldout, int bx, int by,
                                        float (*t)[33])
{
    const int k0 = by * 32, n0 = bx * 32;
    const int tx = threadIdx.x & 31, ty = threadIdx.x >> 5;
    #pragma unroll
    for (int r = 0; r < 32; r += 8)
        t[ty + r][tx] = in[(long long)(k0 + ty + r) * ldin + n0 + tx];
    __syncthreads();
    #pragma unroll
    for (int r = 0; r < 32; r += 8)
        out[(long long)(n0 + ty + r) * ldout + k0 + tx] = f2tff(t[tx][ty + r]);
}

__global__ __launch_bounds__(256)
void prep_all(const float4* __restrict__ hidden4, float4* __restrict__ hid4,
              const float* __restrict__ Wqa, const float* __restrict__ Wkva,
              const float* __restrict__ Wqb, const float* __restrict__ Wkvb,
              const float* __restrict__ Wo,
              float* __restrict__ wct, float* __restrict__ wqbt,
              float* __restrict__ wkvbt, float* __restrict__ wot)
{
    __shared__ float t[32][33];
    int b = blockIdx.x;
    if (b < PREP_RB) {
        int i = b * 256 + threadIdx.x;
        float4 v = hidden4[i];
        v.x = f2tff(v.x); v.y = f2tff(v.y); v.z = f2tff(v.z); v.w = f2tff(v.w);
        hid4[i] = v;
    } else if (b < PREP_WQA) {
        int idx = b - PREP_RB;
        tr_tile(Wqa, wct, Q_LORA, HIDDEN, idx % 48, idx / 48, t);
    } else if (b < PREP_WKVA) {
        int idx = b - PREP_WQA;
        tr_tile(Wkva, wct + (long long)Q_LORA * HIDDEN, NC - Q_LORA, HIDDEN,
                idx % 18, idx / 18, t);
    } else if (b < PREP_WQB) {
        int idx = b - PREP_WKVA;
        tr_tile(Wqb, wqbt, 3072, Q_LORA, idx % 96, idx / 96, t);
    } else if (b < PREP_WKVB) {
        int idx = b - PREP_WQB;
        tr_tile(Wkvb, wkvbt, 4096, KV_LORA, idx % 128, idx / 128, t);
    } else {
        int idx = b - PREP_WKVB;
        tr_tile(Wo, wot, HIDDEN, HIDDEN, idx % 64, idx / 64, t);
    }
}

// ---------------- C = alpha * A(MxK) @ B^T; A,B k-major, BOTH tf32 ---------
__global__ __launch_bounds__(256, 2)
void mm_nt(const float* __restrict__ A, const float* __restrict__ B,
           float* __restrict__ C,
           int M, int N, int K, int lda, int ldb, int ldc,
           float alpha, int store_tf32)
{
    extern __shared__ float smem[];
    const uint32_t sbase = (uint32_t)__cvta_generic_to_shared(smem);

    const int bm = blockIdx.y * BM, bn = blockIdx.x * BN;

    const int tid  = threadIdx.x;
    const int lane = tid & 31, wid = tid >> 5;
    const int wm = (wid & 1) * 64, wn = (wid >> 1) * 32;
    const int lr = lane >> 2, lc = lane & 3;

    const int iters = K / BK;

    float acc[4][4][4] = {};

    auto load_stage = [&](int s, int k0) {
        uint32_t sa = sbase + (uint32_t)(s * NT_STG_WORDS) * 4u;
        uint32_t sb = sa + NT_A_WORDS * 4u;
        #pragma unroll
        for (int i = 0; i < 4; i++) {
            int ch = tid + i * 256;
            int row = ch >> 3, kc = (ch & 7) * 4;
            cpa16(sa + (uint32_t)(row * AP + kc) * 4u,
                  A + (long long)(bm + row) * lda + k0 + kc, true);
        }
        #pragma unroll
        for (int i = 0; i < 4; i++) {
            int ch = tid + i * 256;
            int row = ch >> 3, kc = (ch & 7) * 4;
            cpa16(sb + (uint32_t)(row * AP + kc) * 4u,
                  B + (long long)(bn + row) * ldb + k0 + kc, (bn + row) < N);
        }
    };

    load_stage(0, 0);
    CP_COMMIT();

    const int arow  = (lane & 7) + ((lane >> 3) & 1) * 8;
    const int akoff = (lane >> 4) * 4;
    const int brow  = (lane & 7) + (lane >> 4) * 8;
    const int bkoff = ((lane >> 3) & 1) * 4;

    for (int it = 0; it < iters; it++) {
        const int s = it % 3;
        if (it + 1 < iters) {
            load_stage((it + 1) % 3, (it + 1) * BK);
            CP_COMMIT();
            CP_WAIT1();
        } else {
            CP_WAIT0();
        }
        __syncthreads();

        uint32_t sa = sbase + (uint32_t)(s * NT_STG_WORDS) * 4u;
        uint32_t sb = sa + NT_A_WORDS * 4u;

        #pragma unroll
        for (int ks = 0; ks < BK; ks += 8) {
            uint32_t af[4][4], bf[4][2];
            #pragma unroll
            for (int mt = 0; mt < 4; mt++) {
                uint32_t addr = sa + (uint32_t)((wm + mt * 16 + arow) * AP + ks + akoff) * 4u;
                ldsm4(af[mt][0], af[mt][1], af[mt][2], af[mt][3], addr);
            }
            #pragma unroll
            for (int nt = 0; nt < 4; nt += 2) {
                uint32_t addr = sb + (uint32_t)((wn + nt * 8 + brow) * AP + ks + bkoff) * 4u;
                ldsm4(bf[nt][0], bf[nt][1], bf[nt + 1][0], bf[nt + 1][1], addr);
            }
            #pragma unroll
            for (int mt = 0; mt < 4; mt++)
                #pragma unroll
                for (int nt = 0; nt < 4; nt++)
                    mma8(acc[mt][nt], af[mt], bf[nt]);
        }
    }

    #pragma unroll
    for (int mt = 0; mt < 4; mt++) {
        int r0 = bm + wm + mt * 16 + lr;
        #pragma unroll
        for (int nt = 0; nt < 4; nt++) {
            int c = bn + wn + nt * 8 + 2 * lc;
            if (c < N) {
                float v00 = alpha * acc[mt][nt][0], v01 = alpha * acc[mt][nt][1];
                float v10 = alpha * acc[mt][nt][2], v11 = alpha * acc[mt][nt][3];
                if (store_tf32) {
                    v00 = f2tff(v00); v01 = f2tff(v01);
                    v10 = f2tff(v10); v11 = f2tff(v11);
                }
                C[(long long)r0 * ldc + c]           = v00;
                C[(long long)r0 * ldc + c + 1]       = v01;
                C[(long long)(r0 + 8) * ldc + c]     = v10;
                C[(long long)(r0 + 8) * ldc + c + 1] = v11;
            }
        }
    }
}

// ---------------- RMSNorm (tf32 out) ----------------
__global__ __launch_bounds__(256)
void rmsnorm_k(const float* __restrict__ in, const float* __restrict__ w,
               float* __restrict__ out, int n, int ld_in, int ld_out)
{
    const int t = blockIdx.x;
    const float* x = in + (long long)t * ld_in;
    float* o = out + (long long)t * ld_out;

    float s = 0.f;
    for (int i = threadIdx.x; i < n; i += blockDim.x) {
        float v = x[i];
        s += v * v;
    }
    __shared__ float red[8];
    __shared__ float tot;
    #pragma unroll
    for (int off = 16; off; off >>= 1) s += __shfl_xor_sync(0xffffffffu, s, off);
    if ((threadIdx.x & 31) == 0) red[threadIdx.x >> 5] = s;
    __syncthreads();
    if (threadIdx.x < 32) {
        float v = (threadIdx.x < 8) ? red[threadIdx.x] : 0.f;
        #pragma unroll
        for (int off = 4; off; off >>= 1) v += __shfl_xor_sync(0xffffffffu, v, off);
        if (threadIdx.x == 0) tot = v;
    }
    __syncthreads();
    float scale = 1.0f / sqrtf(tot / (float)n + 1e-6f);
    for (int i = threadIdx.x; i < n; i += blockDim.x)
        o[i] = f2tff(x[i] * scale * w[i]);
}

// ---------------- RoPE: q in place + kf assembly ----------------
__global__ __launch_bounds__(256)
void rope_assemble(float* __restrict__ q, const float* __restrict__ kv,
                   const float* __restrict__ qkva, float* __restrict__ kf, int T)
{
    const int t = blockIdx.x;
    __shared__ float cs[32], sn[32];
    if (threadIdx.x < 32) {
        double fr = (double)t * pow(10000.0, -(double)threadIdx.x / 32.0);
        cs[threadIdx.x] = (float)cos(fr);
        sn[threadIdx.x] = (float)sin(fr);
    }
    __syncthreads();

    for (int i = threadIdx.x; i < N_HEADS * QK_NOPE; i += blockDim.x) {
        int h = i >> 7, d = i & 127;
        kf[(long long)t * 3072 + h * QK_HEAD + d] = kv[(long long)t * 4096 + h * 256 + d];
    }
    for (int i = threadIdx.x; i < N_HEADS * 32; i += blockDim.x) {
        int h = i >> 5, p = i & 31;
        float c = cs[p], s = sn[p];

        long long qoff = (long long)t * 3072 + h * QK_HEAD + QK_NOPE + 2 * p;
        float x1 = q[qoff], x2 = q[qoff + 1];
        q[qoff]     = f2tff(x1 * c - x2 * s);
        q[qoff + 1] = f2tff(x2 * c + x1 * s);

        long long koff = (long long)t * NC + (Q_LORA + KV_LORA) + 2 * p;
        float k1 = qkva[koff], k2 = qkva[koff + 1];
        long long foff = (long long)t * 3072 + h * QK_HEAD + QK_NOPE + 2 * p;
        kf[foff]     = f2tff(k1 * c - k2 * s);
        kf[foff + 1] = f2tff(k2 * c + k1 * s);
    }
}

// ---------------- V transpose ----------------
__global__ __launch_bounds__(256)
void transpose_v(const float* __restrict__ kv, float* __restrict__ vt, int T)
{
    __shared__ float tile[32][129];
    const int t0 = blockIdx.x * 32, h = blockIdx.y;
    #pragma unroll
    for (int c = 0; c < 16; c++) {
        int idx = threadIdx.x + c * 256;
        int tt = idx >> 7, vd = idx & 127;
        tile[tt][vd] = kv[(long long)(t0 + tt) * 4096 + h * 256 + 128 + vd];
    }
    __syncthreads();
    #pragma unroll
    for (int c = 0; c < 16; c++) {
        int idx = threadIdx.x + c * 256;
        int vd = idx >> 5, tt = idx & 31;
        vt[(long long)h * (V_DIM * T_MAX) + (long long)vd * T_MAX + t0 + tt] = tile[tt][vd];
    }
}

// ---------------- fused flash attention (tf32, base-2 softmax, Q in regs) --
// R13 layout; single barrier per tile (loads issued AFTER the barrier).
#define QP 196
#define VP 36
#define PP 36
#define SQ_OFF 0
#define SK_STG (32 * QP)
#define SK_OFF (128 * QP)
#define SV_STG (128 * VP)
#define SV_OFF (SK_OFF + 2 * SK_STG)
#define SP_OFF (SV_OFF + 2 * SV_STG)
#define FL_SMEM_WORDS (SP_OFF + 128 * PP)
#define FL_SMEM_BYTES (FL_SMEM_WORDS * 4)   // 205824

__global__ __launch_bounds__(256, 1)
void flash_attn(const float* __restrict__ qf, const float* __restrict__ kf,
                const float* __restrict__ vt, float* __restrict__ at, int T)
{
    extern __shared__ float smem[];
    const uint32_t sbase = (uint32_t)__cvta_generic_to_shared(smem);

    const int i = (int)gridDim.x - 1 - (int)blockIdx.x;   // heavy blocks first
    const int h = blockIdx.y;
    const int tid  = threadIdx.x;
    const int lane = tid & 31, wid = tid >> 5;
    const int wrb  = wid * 16;
    const int lr = lane >> 2, lc = lane & 3;
    const int gr0 = i * 128 + wrb;

    const int arow  = (lane & 7) + ((lane >> 3) & 1) * 8;
    const int akoff = (lane >> 4) * 4;
    const int brow  = (lane & 7) + (lane >> 4) * 8;
    const int bkoff = ((lane >> 3) & 1) * 4;

    const int NT = 4 * (i + 1);
    const float cexp = 0.07216878364870322f * 1.4426950408889634f;

    // --- stage Q ---
    #pragma unroll
    for (int c = 0; c < 24; c++) {
        int ch = tid + c * 256;
        int row = ch / 48, c4 = (ch % 48) * 4;
        cpa16(sbase + (uint32_t)(SQ_OFF + row * QP + c4) * 4u,
              qf + (long long)(i * 128 + row) * 3072 + h * QK_HEAD + c4, true);
    }

    auto load_kv = [&](int s, int j) {
        uint32_t skb = sbase + (uint32_t)(SK_OFF + s * SK_STG) * 4u;
        #pragma unroll
        for (int c = 0; c < 6; c++) {
            int ch = tid + c * 256;
            int row = ch / 48, c4 = (ch % 48) * 4;
            cpa16(skb + (uint32_t)(row * QP + c4) * 4u,
                  kf + (long long)(j * 32 + row) * 3072 + h * QK_HEAD + c4, true);
        }
        uint32_t svb = sbase + (uint32_t)(SV_OFF + s * SV_STG) * 4u;
        #pragma unroll
        for (int c = 0; c < 4; c++) {
            int ch = tid + c * 256;
            int row = ch >> 3, c4 = (ch & 7) * 4;
            cpa16(svb + (uint32_t)(row * VP + c4) * 4u,
                  vt + (long long)h * (V_DIM * T_MAX) + (long long)row * T_MAX + j * 32 + c4,
                  true);
        }
    };

    load_kv(0, 0);
    CP_COMMIT();
    CP_WAIT0();
    __syncthreads();

    // --- hoist Q fragments into registers ---
    const uint32_t sqb = sbase + (uint32_t)SQ_OFF * 4u;
    uint32_t qreg[24][4];
    #pragma unroll
    for (int ks8 = 0; ks8 < 24; ks8++)
        ldsm4(qreg[ks8][0], qreg[ks8][1], qreg[ks8][2], qreg[ks8][3],
              sqb + (uint32_t)((wrb + arow) * QP + ks8 * 8 + akoff) * 4u);

    float m0 = -FLT_MAX, m1 = -FLT_MAX, l0 = 0.f, l1 = 0.f;
    float oa[16][4];
    #pragma unroll
    for (int nt = 0; nt < 16; nt++)
        #pragma unroll
        for (int v = 0; v < 4; v++) oa[nt][v] = 0.f;

    const uint32_t spb = sbase + (uint32_t)SP_OFF * 4u;

    for (int j = 0; j < NT; j++) {
        const int s = j & 1;
        // wait for stage j, then barrier, THEN issue next load:
        // all warps are past iteration j-1 reads, so overwriting stage
        // (j+1)&1 is WAR-safe without a trailing barrier.
        CP_WAIT0();
        __syncthreads();
        if (j + 1 < NT) {
            load_kv((j + 1) & 1, j + 1);
            CP_COMMIT();
        }

        const uint32_t skb = sbase + (uint32_t)(SK_OFF + s * SK_STG) * 4u;
        float sc[4][4];
        #pragma unroll
        for (int nt = 0; nt < 4; nt++)
            #pragma unroll
            for (int v = 0; v < 4; v++) sc[nt][v] = 0.f;

        #pragma unroll
        for (int ks8 = 0; ks8 < 24; ks8++) {
            uint32_t b[4][2];
            ldsm4(b[0][0], b[0][1], b[1][0], b[1][1],
                  skb + (uint32_t)(brow * QP + ks8 * 8 + bkoff) * 4u);
            ldsm4(b[2][0], b[2][1], b[3][0], b[3][1],
                  skb + (uint32_t)((16 + brow) * QP + ks8 * 8 + bkoff) * 4u);
            #pragma unroll
            for (int nt = 0; nt < 4; nt++) mma8(sc[nt], qreg[ks8], b[nt]);
        }

        if (j >= i * 4) {
            #pragma unroll
            for (int nt = 0; nt < 4; nt++)
                #pragma unroll
                for (int v = 0; v < 4; v++) {
                    int kg = j * 32 + nt * 8 + 2 * lc + (v & 1);
                    int rr = gr0 + lr + ((v >> 1) ? 8 : 0);
                    if (kg > rr) sc[nt][v] = -FLT_MAX;
                }
        }

        float mx0 = -FLT_MAX, mx1 = -FLT_MAX;
        #pragma unroll
        for (int nt = 0; nt < 4; nt++) {
            mx0 = fmaxf(mx0, fmaxf(sc[nt][0], sc[nt][1]));
            mx1 = fmaxf(mx1, fmaxf(sc[nt][2], sc[nt][3]));
        }
        mx0 = fmaxf(mx0, __shfl_xor_sync(0xffffffffu, mx0, 1));
        mx0 = fmaxf(mx0, __shfl_xor_sync(0xffffffffu, mx0, 2));
        mx1 = fmaxf(mx1, __shfl_xor_sync(0xffffffffu, mx1, 1));
        mx1 = fmaxf(mx1, __shfl_xor_sync(0xffffffffu, mx1, 2));

        float mn0 = fmaxf(m0, mx0), mn1 = fmaxf(m1, mx1);
        float c0 = ex2(cexp * (m0 - mn0)), c1 = ex2(cexp * (m1 - mn1));
        float mc0 = cexp * mn0, mc1 = cexp * mn1;

        float sum0 = 0.f, sum1 = 0.f;
        #pragma unroll
        for (int nt = 0; nt < 4; nt++) {
            float p00 = ex2(fmaf(sc[nt][0], cexp, -mc0));
            float p01 = ex2(fmaf(sc[nt][1], cexp, -mc0));
            float p10 = ex2(fmaf(sc[nt][2], cexp, -mc1));
            float p11 = ex2(fmaf(sc[nt][3], cexp, -mc1));
            sum0 += p00 + p01; sum1 += p10 + p11;
            float* pr0 = smem + SP_OFF + (wrb + lr) * PP + nt * 8 + 2 * lc;
            float* pr1 = smem + SP_OFF + (wrb + lr + 8) * PP + nt * 8 + 2 * lc;
            pr0[0] = f2tff(p00); pr0[1] = f2tff(p01);
            pr1[0] = f2tff(p10); pr1[1] = f2tff(p11);
        }
        sum0 += __shfl_xor_sync(0xffffffffu, sum0, 1);
        sum0 += __shfl_xor_sync(0xffffffffu, sum0, 2);
        sum1 += __shfl_xor_sync(0xffffffffu, sum1, 1);
        sum1 += __shfl_xor_sync(0xffffffffu, sum1, 2);

        l0 = l0 * c0 + sum0; l1 = l1 * c1 + sum1;
        m0 = mn0; m1 = mn1;

        #pragma unroll
        for (int nt = 0; nt < 16; nt++) {
            oa[nt][0] *= c0; oa[nt][1] *= c0;
            oa[nt][2] *= c1; oa[nt][3] *= c1;
        }
        __syncwarp();

        const uint32_t svb = sbase + (uint32_t)(SV_OFF + s * SV_STG) * 4u;
        #pragma unroll
        for (int ks = 0; ks < 32; ks += 8) {
            uint32_t a[4];
            ldsm4(a[0], a[1], a[2], a[3],
                  spb + (uint32_t)((wrb + arow) * PP + ks + akoff) * 4u);
            #pragma unroll
            for (int n2 = 0; n2 < 8; n2++) {
                uint32_t b[2][2];
                ldsm4(b[0][0], b[0][1], b[1][0], b[1][1],
                      svb + (uint32_t)((n2 * 16 + brow) * VP + ks + bkoff) * 4u);
                mma8(oa[2 * n2], a, b[0]);
                mma8(oa[2 * n2 + 1], a, b[1]);
            }
        }
        // no trailing barrier: next iteration's barrier provides the WAR guard
    }

    float inv0 = 1.0f / l0, inv1 = 1.0f / l1;
    const long long r0 = (long long)(gr0 + lr) * 2048;
    const long long r1 = (long long)(gr0 + lr + 8) * 2048;
    #pragma unroll
    for (int nt = 0; nt < 16; nt++) {
        int col = h * V_DIM + nt * 8 + 2 * lc;
        at[r0 + col]     = f2tff(oa[nt][0] * inv0);
        at[r0 + col + 1] = f2tff(oa[nt][1] * inv0);
        at[r1 + col]     = f2tff(oa[nt][2] * inv1);
        at[r1 + col + 1] = f2tff(oa[nt][3] * inv1);
    }
}

// ---------------- launch ----------------
extern "C" void kernel_launch(void* const* d_in, const int* in_sizes, int n_in,
                              void* d_out, int out_size)
{
    const float* hidden = (const float*)d_in[0];
    const float* Wqa   = (const float*)d_in[2];
    const float* q_ln  = (const float*)d_in[3];
    const float* Wqb   = (const float*)d_in[4];
    const float* Wkva  = (const float*)d_in[5];
    const float* kv_ln = (const float*)d_in[6];
    const float* Wkvb  = (const float*)d_in[7];
    const float* Wo    = (const float*)d_in[8];
    float* out = (float*)d_out;

    const int T = in_sizes[0] / HIDDEN;   // 4096

    static float *hid = nullptr, *wct = nullptr, *wqbt = nullptr,
                 *wkvbt = nullptr, *wot = nullptr, *qkva = nullptr,
                 *kvn = nullptr, *kv = nullptr, *q = nullptr, *kf = nullptr,
                 *vt = nullptr, *at = nullptr;
    if (!hid) {
        cudaGetSymbolAddress((void**)&hid,   g_hid);
        cudaGetSymbolAddress((void**)&wct,   g_wct);
        cudaGetSymbolAddress((void**)&wqbt,  g_wqbt);
        cudaGetSymbolAddress((void**)&wkvbt, g_wkvbt);
        cudaGetSymbolAddress((void**)&wot,   g_wot);
        cudaGetSymbolAddress((void**)&qkva,  g_qkva);
        cudaGetSymbolAddress((void**)&kvn,   g_kvn);
        cudaGetSymbolAddress((void**)&kv,    g_kv);
        cudaGetSymbolAddress((void**)&q,     g_q);
        cudaGetSymbolAddress((void**)&kf,    g_kf);
        cudaGetSymbolAddress((void**)&vt,    g_vt);
        cudaGetSymbolAddress((void**)&at,    g_at);
        cudaFuncSetAttribute(mm_nt, cudaFuncAttributeMaxDynamicSharedMemorySize, NT_SMEM_BYTES);
        cudaFuncSetAttribute(flash_attn, cudaFuncAttributeMaxDynamicSharedMemorySize, FL_SMEM_BYTES);
    }

    const dim3 thr(256);

    // fused prep (1 launch)
    prep_all<<<PREP_TOTAL, thr>>>(
        (const float4*)hidden, (float4*)hid,
        Wqa, Wkva, Wqb, Wkvb, Wo, wct, wqbt, wkvbt, wot);

    // qkva = hid @ Wc^T
    mm_nt<<<dim3((NC + BN - 1) / BN, T / BM), thr, NT_SMEM_BYTES>>>(
        hid, wct, qkva, T, NC, HIDDEN, HIDDEN, HIDDEN, NC, 1.f, 0);
    // rmsnorms (tf32 out)
    rmsnorm_k<<<T, 256>>>(qkva, q_ln, qkva, Q_LORA, NC, NC);
    rmsnorm_k<<<T, 256>>>(qkva + Q_LORA, kv_ln, kvn, KV_LORA, NC, KV_LORA);
    // q = q_latent @ Wqb^T (tf32 out)
    mm_nt<<<dim3(3072 / BN, T / BM), thr, NT_SMEM_BYTES>>>(
        qkva, wqbt, q, T, 3072, Q_LORA, NC, Q_LORA, 3072, 1.f, 1);
    // kv = kvn @ Wkvb^T (tf32 out)
    mm_nt<<<dim3(4096 / BN, T / BM), thr, NT_SMEM_BYTES>>>(
        kvn, wkvbt, kv, T, 4096, KV_LORA, KV_LORA, KV_LORA, 4096, 1.f, 1);
    // rope q in place + build kf
    rope_assemble<<<T, 256>>>(q, kv, qkva, kf, T);
    // V transpose
    transpose_v<<<dim3(T / 32, N_HEADS), thr>>>(kv, vt, T);
    // fused attention
    flash_attn<<<dim3(T / 128, N_HEADS), thr, FL_SMEM_BYTES>>>(q, kf, vt, at, T);
    // out = at @ Wo^T
    mm_nt<<<dim3(HIDDEN / BN, T / BM), thr, NT_SMEM_BYTES>>>(
        at, wot, out, T, HIDDEN, HIDDEN, HIDDEN, HIDDEN, HIDDEN, 1.f, 0);
}

// round 16
// speedup vs baseline: 1.0626x; 1.0493x over previous
#include <cuda_runtime.h>
#include <float.h>
#include <math.h>
#include <stdint.h>

// ---------------- problem constants ----------------
#define HIDDEN   2048
#define N_HEADS  16
#define QK_NOPE  128
#define QK_ROPE  64
#define V_DIM    128
#define Q_LORA   1536
#define KV_LORA  512
#define QK_HEAD  192
#define T_MAX    4096
#define NC       2112   // Q_LORA + KV_LORA + QK_ROPE

// ---------------- scratch ----------------
__device__ float g_hid  [T_MAX * HIDDEN];
__device__ float g_wct  [NC * HIDDEN];
__device__ float g_wqbt [3072 * Q_LORA];
__device__ float g_wkvbt[4096 * KV_LORA];
__device__ float g_wot  [HIDDEN * HIDDEN];
__device__ float g_qkva [T_MAX * NC];
__device__ float g_kvn  [T_MAX * KV_LORA];
__device__ float g_kv   [T_MAX * N_HEADS * (QK_NOPE + V_DIM)];
__device__ float g_q    [T_MAX * N_HEADS * QK_HEAD];
__device__ float g_kpe  [T_MAX * QK_ROPE];
__device__ float g_vt   [N_HEADS * V_DIM * T_MAX];
__device__ float g_at   [T_MAX * N_HEADS * V_DIM];

// ---------------- helpers ----------------
__device__ __forceinline__ uint32_t f2tf(float f) {
    uint32_t u;
    asm("cvt.rna.tf32.f32 %0, %1;" : "=r"(u) : "f"(f));
    return u;
}
__device__ __forceinline__ float f2tff(float f) { return __uint_as_float(f2tf(f)); }

__device__ __forceinline__ float ex2(float x) {
    float y;
    asm("ex2.approx.ftz.f32 %0, %1;" : "=f"(y) : "f"(x));
    return y;
}

__device__ __forceinline__ void mma8(float* c, const uint32_t* a, const uint32_t* b) {
    asm volatile(
        "mma.sync.aligned.m16n8k8.row.col.f32.tf32.tf32.f32 "
        "{%0,%1,%2,%3}, {%4,%5,%6,%7}, {%8,%9}, {%0,%1,%2,%3};\n"
        : "+f"(c[0]), "+f"(c[1]), "+f"(c[2]), "+f"(c[3])
        : "r"(a[0]), "r"(a[1]), "r"(a[2]), "r"(a[3]), "r"(b[0]), "r"(b[1]));
}

__device__ __forceinline__ void ldsm4(uint32_t& r0, uint32_t& r1, uint32_t& r2,
                                      uint32_t& r3, uint32_t addr) {
    asm volatile("ldmatrix.sync.aligned.m8n8.x4.shared.b16 {%0,%1,%2,%3}, [%4];\n"
                 : "=r"(r0), "=r"(r1), "=r"(r2), "=r"(r3) : "r"(addr));
}

__device__ __forceinline__ void cpa16(uint32_t dst, const void* src, bool valid) {
    int sz = valid ? 16 : 0;
    asm volatile("cp.async.cg.shared.global [%0], [%1], 16, %2;\n"
                 :: "r"(dst), "l"(src), "r"(sz));
}
#define CP_COMMIT() asm volatile("cp.async.commit_group;\n")
#define CP_WAIT1()  asm volatile("cp.async.wait_group 1;\n")
#define CP_WAIT0()  asm volatile("cp.async.wait_group 0;\n")

#define BM 128
#define BN 128
#define BK 32
#define AP 36

#define NT_A_WORDS (BM * AP)
#define NT_STG_WORDS (2 * NT_A_WORDS)
#define NT_SMEM_BYTES (3 * NT_STG_WORDS * 4)

// ---------------- fused prep ----------------
#define PREP_RB     8192
#define PREP_WQA    (PREP_RB + 3072)
#define PREP_WKVA   (PREP_WQA + 1152)
#define PREP_WQB    (PREP_WKVA + 4608)
#define PREP_WKVB   (PREP_WQB + 2048)
#define PREP_TOTAL  (PREP_WKVB + 4096)

__device__ __forceinline__ void tr_tile(const float* __restrict__ in,
                                        float* __restrict__ out,
                                        int ldin, int ldout, int bx, int by,
                                        float (*t)[33])
{
    const int k0 = by * 32, n0 = bx * 32;
    const int tx = threadIdx.x & 31, ty = threadIdx.x >> 5;
    #pragma unroll
    for (int r = 0; r < 32; r += 8)
        t[ty + r][tx] = in[(long long)(k0 + ty + r) * ldin + n0 + tx];
    __syncthreads();
    #pragma unroll
    for (int r = 0; r < 32; r += 8)
        out[(long long)(n0 + ty + r) * ldout + k0 + tx] = f2tff(t[tx][ty + r]);
}

__global__ __launch_bounds__(256)
void prep_all(const float4* __restrict__ hidden4, float4* __restrict__ hid4,
              const float* __restrict__ Wqa, const float* __restrict__ Wkva,
              const float* __restrict__ Wqb, const float* __restrict__ Wkvb,
              const float* __restrict__ Wo,
              float* __restrict__ wct, float* __restrict__ wqbt,
              float* __restrict__ wkvbt, float* __restrict__ wot)
{
    __shared__ float t[32][33];
    int b = blockIdx.x;
    if (b < PREP_RB) {
        int i = b * 256 + threadIdx.x;
        float4 v = hidden4[i];
        v.x = f2tff(v.x); v.y = f2tff(v.y); v.z = f2tff(v.z); v.w = f2tff(v.w);
        hid4[i] = v;
    } else if (b < PREP_WQA) {
        int idx = b - PREP_RB;
        tr_tile(Wqa, wct, Q_LORA, HIDDEN, idx % 48, idx / 48, t);
    } else if (b < PREP_WKVA) {
        int idx = b - PREP_WQA;
        tr_tile(Wkva, wct + (long long)Q_LORA * HIDDEN, NC - Q_LORA, HIDDEN,
                idx % 18, idx / 18, t);
    } else if (b < PREP_WQB) {
        int idx = b - PREP_WKVA;
        tr_tile(Wqb, wqbt, 3072, Q_LORA, idx % 96, idx / 96, t);
    } else if (b < PREP_WKVB) {
        int idx = b - PREP_WQB;
        tr_tile(Wkvb, wkvbt, 4096, KV_LORA, idx % 128, idx / 128, t);
    } else {
        int idx = b - PREP_WKVB;
        tr_tile(Wo, wot, HIDDEN, HIDDEN, idx % 64, idx / 64, t);
    }
}

// ---------------- C = alpha * A(MxK) @ B^T; A,B k-major, BOTH tf32 ---------
__global__ __launch_bounds__(256, 2)
void mm_nt(const float* __restrict__ A, const float* __restrict__ B,
           float* __restrict__ C,
           int M, int N, int K, int lda, int ldb, int ldc,
           float alpha, int store_tf32)
{
    extern __shared__ float smem[];
    const uint32_t sbase = (uint32_t)__cvta_generic_to_shared(smem);

    const int bm = blockIdx.y * BM, bn = blockIdx.x * BN;

    const int tid  = threadIdx.x;
    const int lane = tid & 31, wid = tid >> 5;
    const int wm = (wid & 1) * 64, wn = (wid >> 1) * 32;
    const int lr = lane >> 2, lc = lane & 3;

    const int iters = K / BK;

    float acc[4][4][4] = {};

    auto load_stage = [&](int s, int k0) {
        uint32_t sa = sbase + (uint32_t)(s * NT_STG_WORDS) * 4u;
        uint32_t sb = sa + NT_A_WORDS * 4u;
        #pragma unroll
        for (int i = 0; i < 4; i++) {
            int ch = tid + i * 256;
            int row = ch >> 3, kc = (ch & 7) * 4;
            cpa16(sa + (uint32_t)(row * AP + kc) * 4u,
                  A + (long long)(bm + row) * lda + k0 + kc, true);
        }
        #pragma unroll
        for (int i = 0; i < 4; i++) {
            int ch = tid + i * 256;
            int row = ch >> 3, kc = (ch & 7) * 4;
            cpa16(sb + (uint32_t)(row * AP + kc) * 4u,
                  B + (long long)(bn + row) * ldb + k0 + kc, (bn + row) < N);
        }
    };

    load_stage(0, 0);
    CP_COMMIT();

    const int arow  = (lane & 7) + ((lane >> 3) & 1) * 8;
    const int akoff = (lane >> 4) * 4;
    const int brow  = (lane & 7) + (lane >> 4) * 8;
    const int bkoff = ((lane >> 3) & 1) * 4;

    for (int it = 0; it < iters; it++) {
        const int s = it % 3;
        if (it + 1 < iters) {
            load_stage((it + 1) % 3, (it + 1) * BK);
            CP_COMMIT();
            CP_WAIT1();
        } else {
            CP_WAIT0();
        }
        __syncthreads();

        uint32_t sa = sbase + (uint32_t)(s * NT_STG_WORDS) * 4u;
        uint32_t sb = sa + NT_A_WORDS * 4u;

        #pragma unroll
        for (int ks = 0; ks < BK; ks += 8) {
            uint32_t af[4][4], bf[4][2];
            #pragma unroll
            for (int mt = 0; mt < 4; mt++) {
                uint32_t addr = sa + (uint32_t)((wm + mt * 16 + arow) * AP + ks + akoff) * 4u;
                ldsm4(af[mt][0], af[mt][1], af[mt][2], af[mt][3], addr);
            }
            #pragma unroll
            for (int nt = 0; nt < 4; nt += 2) {
                uint32_t addr = sb + (uint32_t)((wn + nt * 8 + brow) * AP + ks + bkoff) * 4u;
                ldsm4(bf[nt][0], bf[nt][1], bf[nt + 1][0], bf[nt + 1][1], addr);
            }
            #pragma unroll
            for (int mt = 0; mt < 4; mt++)
                #pragma unroll
                for (int nt = 0; nt < 4; nt++)
                    mma8(acc[mt][nt], af[mt], bf[nt]);
        }
    }

    #pragma unroll
    for (int mt = 0; mt < 4; mt++) {
        int r0 = bm + wm + mt * 16 + lr;
        #pragma unroll
        for (int nt = 0; nt < 4; nt++) {
            int c = bn + wn + nt * 8 + 2 * lc;
            if (c < N) {
                float v00 = alpha * acc[mt][nt][0], v01 = alpha * acc[mt][nt][1];
                float v10 = alpha * acc[mt][nt][2], v11 = alpha * acc[mt][nt][3];
                if (store_tf32) {
                    v00 = f2tff(v00); v01 = f2tff(v01);
                    v10 = f2tff(v10); v11 = f2tff(v11);
                }
                C[(long long)r0 * ldc + c]           = v00;
                C[(long long)r0 * ldc + c + 1]       = v01;
                C[(long long)(r0 + 8) * ldc + c]     = v10;
                C[(long long)(r0 + 8) * ldc + c + 1] = v11;
            }
        }
    }
}

// ---------------- RMSNorm (tf32 out) ----------------
__global__ __launch_bounds__(256)
void rmsnorm_k(const float* __restrict__ in, const float* __restrict__ w,
               float* __restrict__ out, int n, int ld_in, int ld_out)
{
    const int t = blockIdx.x;
    const float* x = in + (long long)t * ld_in;
    float* o = out + (long long)t * ld_out;

    float s = 0.f;
    for (int i = threadIdx.x; i < n; i += blockDim.x) {
        float v = x[i];
        s += v * v;
    }
    __shared__ float red[8];
    __shared__ float tot;
    #pragma unroll
    for (int off = 16; off; off >>= 1) s += __shfl_xor_sync(0xffffffffu, s, off);
    if ((threadIdx.x & 31) == 0) red[threadIdx.x >> 5] = s;
    __syncthreads();
    if (threadIdx.x < 32) {
        float v = (threadIdx.x < 8) ? red[threadIdx.x] : 0.f;
        #pragma unroll
        for (int off = 4; off; off >>= 1) v += __shfl_xor_sync(0xffffffffu, v, off);
        if (threadIdx.x == 0) tot = v;
    }
    __syncthreads();
    float scale = 1.0f / sqrtf(tot / (float)n + 1e-6f);
    for (int i = threadIdx.x; i < n; i += blockDim.x)
        o[i] = f2tff(x[i] * scale * w[i]);
}

// ---------------- RoPE: q in place + kpe (per-token, 64 dims) --------------
__global__ __launch_bounds__(256)
void rope_q_kpe(float* __restrict__ q, const float* __restrict__ qkva,
                float* __restrict__ kpe, int T)
{
    const int t = blockIdx.x;
    __shared__ float cs[32], sn[32];
    if (threadIdx.x < 32) {
        double fr = (double)t * pow(10000.0, -(double)threadIdx.x / 32.0);
        cs[threadIdx.x] = (float)cos(fr);
        sn[threadIdx.x] = (float)sin(fr);
    }
    __syncthreads();

    for (int i = threadIdx.x; i < N_HEADS * 32; i += blockDim.x) {
        int h = i >> 5, p = i & 31;
        float c = cs[p], s = sn[p];
        long long qoff = (long long)t * 3072 + h * QK_HEAD + QK_NOPE + 2 * p;
        float x1 = q[qoff], x2 = q[qoff + 1];
        q[qoff]     = f2tff(x1 * c - x2 * s);
        q[qoff + 1] = f2tff(x2 * c + x1 * s);
    }
    if (threadIdx.x < 32) {
        int p = threadIdx.x;
        float c = cs[p], s = sn[p];
        long long koff = (long long)t * NC + (Q_LORA + KV_LORA) + 2 * p;
        float k1 = qkva[koff], k2 = qkva[koff + 1];
        kpe[t * QK_ROPE + 2 * p]     = f2tff(k1 * c - k2 * s);
        kpe[t * QK_ROPE + 2 * p + 1] = f2tff(k2 * c + k1 * s);
    }
}

// ---------------- V transpose ----------------
__global__ __launch_bounds__(256)
void transpose_v(const float* __restrict__ kv, float* __restrict__ vt, int T)
{
    __shared__ float tile[32][129];
    const int t0 = blockIdx.x * 32, h = blockIdx.y;
    #pragma unroll
    for (int c = 0; c < 16; c++) {
        int idx = threadIdx.x + c * 256;
        int tt = idx >> 7, vd = idx & 127;
        tile[tt][vd] = kv[(long long)(t0 + tt) * 4096 + h * 256 + 128 + vd];
    }
    __syncthreads();
    #pragma unroll
    for (int c = 0; c < 16; c++) {
        int idx = threadIdx.x + c * 256;
        int vd = idx >> 5, tt = idx & 31;
        vt[(long long)h * (V_DIM * T_MAX) + (long long)vd * T_MAX + t0 + tt] = tile[tt][vd];
    }
}

// ---------------- fused flash attention (K read from kv + kpe) -------------
#define QP 196
#define VP 36
#define PP 36
#define SQ_OFF 0
#define SK_STG (32 * QP)
#define SK_OFF (128 * QP)
#define SV_STG (128 * VP)
#define SV_OFF (SK_OFF + 2 * SK_STG)
#define SP_OFF (SV_OFF + 2 * SV_STG)
#define FL_SMEM_WORDS (SP_OFF + 128 * PP)
#define FL_SMEM_BYTES (FL_SMEM_WORDS * 4)   // 205824

__global__ __launch_bounds__(256, 1)
void flash_attn(const float* __restrict__ qf, const float* __restrict__ kv,
                const float* __restrict__ kpe, const float* __restrict__ vt,
                float* __restrict__ at, int T)
{
    extern __shared__ float smem[];
    const uint32_t sbase = (uint32_t)__cvta_generic_to_shared(smem);

    const int i = (int)gridDim.x - 1 - (int)blockIdx.x;   // heavy blocks first
    const int h = blockIdx.y;
    const int tid  = threadIdx.x;
    const int lane = tid & 31, wid = tid >> 5;
    const int wrb  = wid * 16;
    const int lr = lane >> 2, lc = lane & 3;
    const int gr0 = i * 128 + wrb;

    const int arow  = (lane & 7) + ((lane >> 3) & 1) * 8;
    const int akoff = (lane >> 4) * 4;
    const int brow  = (lane & 7) + (lane >> 4) * 8;
    const int bkoff = ((lane >> 3) & 1) * 4;

    const int NT = 4 * (i + 1);
    const float cexp = 0.07216878364870322f * 1.4426950408889634f;

    // --- stage Q ---
    #pragma unroll
    for (int c = 0; c < 24; c++) {
        int ch = tid + c * 256;
        int row = ch / 48, c4 = (ch % 48) * 4;
        cpa16(sbase + (uint32_t)(SQ_OFF + row * QP + c4) * 4u,
              qf + (long long)(i * 128 + row) * 3072 + h * QK_HEAD + c4, true);
    }

    // K tile: nope dims [0,128) from kv, rope dims [128,192) from kpe
    auto load_kv_tile = [&](int s, int j) {
        uint32_t skb = sbase + (uint32_t)(SK_OFF + s * SK_STG) * 4u;
        #pragma unroll
        for (int c = 0; c < 6; c++) {
            int ch = tid + c * 256;
            int row = ch / 48, c4 = (ch % 48) * 4;
            int t = j * 32 + row;
            const float* src = (c4 < QK_NOPE)
                ? kv + (long long)t * 4096 + h * 256 + c4
                : kpe + (long long)t * QK_ROPE + (c4 - QK_NOPE);
            cpa16(skb + (uint32_t)(row * QP + c4) * 4u, src, true);
        }
        uint32_t svb = sbase + (uint32_t)(SV_OFF + s * SV_STG) * 4u;
        #pragma unroll
        for (int c = 0; c < 4; c++) {
            int ch = tid + c * 256;
            int row = ch >> 3, c4 = (ch & 7) * 4;
            cpa16(svb + (uint32_t)(row * VP + c4) * 4u,
                  vt + (long long)h * (V_DIM * T_MAX) + (long long)row * T_MAX + j * 32 + c4,
                  true);
        }
    };

    load_kv_tile(0, 0);
    CP_COMMIT();
    CP_WAIT0();
    __syncthreads();

    // --- hoist Q fragments into registers ---
    const uint32_t sqb = sbase + (uint32_t)SQ_OFF * 4u;
    uint32_t qreg[24][4];
    #pragma unroll
    for (int ks8 = 0; ks8 < 24; ks8++)
        ldsm4(qreg[ks8][0], qreg[ks8][1], qreg[ks8][2], qreg[ks8][3],
              sqb + (uint32_t)((wrb + arow) * QP + ks8 * 8 + akoff) * 4u);

    float m0 = -FLT_MAX, m1 = -FLT_MAX, l0 = 0.f, l1 = 0.f;
    float oa[16][4];
    #pragma unroll
    for (int nt = 0; nt < 16; nt++)
        #pragma unroll
        for (int v = 0; v < 4; v++) oa[nt][v] = 0.f;

    const uint32_t spb = sbase + (uint32_t)SP_OFF * 4u;

    for (int j = 0; j < NT; j++) {
        const int s = j & 1;
        CP_WAIT0();
        __syncthreads();
        if (j + 1 < NT) {
            load_kv_tile((j + 1) & 1, j + 1);
            CP_COMMIT();
        }

        const uint32_t skb = sbase + (uint32_t)(SK_OFF + s * SK_STG) * 4u;
        float sc[4][4];
        #pragma unroll
        for (int nt = 0; nt < 4; nt++)
            #pragma unroll
            for (int v = 0; v < 4; v++) sc[nt][v] = 0.f;

        #pragma unroll
        for (int ks8 = 0; ks8 < 24; ks8++) {
            uint32_t b[4][2];
            ldsm4(b[0][0], b[0][1], b[1][0], b[1][1],
                  skb + (uint32_t)(brow * QP + ks8 * 8 + bkoff) * 4u);
            ldsm4(b[2][0], b[2][1], b[3][0], b[3][1],
                  skb + (uint32_t)((16 + brow) * QP + ks8 * 8 + bkoff) * 4u);
            #pragma unroll
            for (int nt = 0; nt < 4; nt++) mma8(sc[nt], qreg[ks8], b[nt]);
        }

        if (j >= i * 4) {
            #pragma unroll
            for (int nt = 0; nt < 4; nt++)
                #pragma unroll
                for (int v = 0; v < 4; v++) {
                    int kg = j * 32 + nt * 8 + 2 * lc + (v & 1);
                    int rr = gr0 + lr + ((v >> 1) ? 8 : 0);
                    if (kg > rr) sc[nt][v] = -FLT_MAX;
                }
        }

        float mx0 = -FLT_MAX, mx1 = -FLT_MAX;
        #pragma unroll
        for (int nt = 0; nt < 4; nt++) {
            mx0 = fmaxf(mx0, fmaxf(sc[nt][0], sc[nt][1]));
            mx1 = fmaxf(mx1, fmaxf(sc[nt][2], sc[nt][3]));
        }
        mx0 = fmaxf(mx0, __shfl_xor_sync(0xffffffffu, mx0, 1));
        mx0 = fmaxf(mx0, __shfl_xor_sync(0xffffffffu, mx0, 2));
        mx1 = fmaxf(mx1, __shfl_xor_sync(0xffffffffu, mx1, 1));
        mx1 = fmaxf(mx1, __shfl_xor_sync(0xffffffffu, mx1, 2));

        float mn0 = fmaxf(m0, mx0), mn1 = fmaxf(m1, mx1);
        float c0 = ex2(cexp * (m0 - mn0)), c1 = ex2(cexp * (m1 - mn1));
        float mc0 = cexp * mn0, mc1 = cexp * mn1;

        float sum0 = 0.f, sum1 = 0.f;
        #pragma unroll
        for (int nt = 0; nt < 4; nt++) {
            float p00 = ex2(fmaf(sc[nt][0], cexp, -mc0));
            float p01 = ex2(fmaf(sc[nt][1], cexp, -mc0));
            float p10 = ex2(fmaf(sc[nt][2], cexp, -mc1));
            float p11 = ex2(fmaf(sc[nt][3], cexp, -mc1));
            sum0 += p00 + p01; sum1 += p10 + p11;
            float* pr0 = smem + SP_OFF + (wrb + lr) * PP + nt * 8 + 2 * lc;
            float* pr1 = smem + SP_OFF + (wrb + lr + 8) * PP + nt * 8 + 2 * lc;
            pr0[0] = f2tff(p00); pr0[1] = f2tff(p01);
            pr1[0] = f2tff(p10); pr1[1] = f2tff(p11);
        }
        sum0 += __shfl_xor_sync(0xffffffffu, sum0, 1);
        sum0 += __shfl_xor_sync(0xffffffffu, sum0, 2);
        sum1 += __shfl_xor_sync(0xffffffffu, sum1, 1);
        sum1 += __shfl_xor_sync(0xffffffffu, sum1, 2);

        l0 = l0 * c0 + sum0; l1 = l1 * c1 + sum1;
        m0 = mn0; m1 = mn1;

        #pragma unroll
        for (int nt = 0; nt < 16; nt++) {
            oa[nt][0] *= c0; oa[nt][1] *= c0;
            oa[nt][2] *= c1; oa[nt][3] *= c1;
        }
        __syncwarp();

        const uint32_t svb = sbase + (uint32_t)(SV_OFF + s * SV_STG) * 4u;
        #pragma unroll
        for (int ks = 0; ks < 32; ks += 8) {
            uint32_t a[4];
            ldsm4(a[0], a[1], a[2], a[3],
                  spb + (uint32_t)((wrb + arow) * PP + ks + akoff) * 4u);
            #pragma unroll
            for (int n2 = 0; n2 < 8; n2++) {
                uint32_t b[2][2];
                ldsm4(b[0][0], b[0][1], b[1][0], b[1][1],
                      svb + (uint32_t)((n2 * 16 + brow) * VP + ks + bkoff) * 4u);
                mma8(oa[2 * n2], a, b[0]);
                mma8(oa[2 * n2 + 1], a, b[1]);
            }
        }
    }

    float inv0 = 1.0f / l0, inv1 = 1.0f / l1;
    const long long r0 = (long long)(gr0 + lr) * 2048;
    const long long r1 = (long long)(gr0 + lr + 8) * 2048;
    #pragma unroll
    for (int nt = 0; nt < 16; nt++) {
        int col = h * V_DIM + nt * 8 + 2 * lc;
        at[r0 + col]     = f2tff(oa[nt][0] * inv0);
        at[r0 + col + 1] = f2tff(oa[nt][1] * inv0);
        at[r1 + col]     = f2tff(oa[nt][2] * inv1);
        at[r1 + col + 1] = f2tff(oa[nt][3] * inv1);
    }
}

// ---------------- launch ----------------
extern "C" void kernel_launch(void* const* d_in, const int* in_sizes, int n_in,
                              void* d_out, int out_size)
{
    const float* hidden = (const float*)d_in[0];
    const float* Wqa   = (const float*)d_in[2];
    const float* q_ln  = (const float*)d_in[3];
    const float* Wqb   = (const float*)d_in[4];
    const float* Wkva  = (const float*)d_in[5];
    const float* kv_ln = (const float*)d_in[6];
    const float* Wkvb  = (const float*)d_in[7];
    const float* Wo    = (const float*)d_in[8];
    float* out = (float*)d_out;

    const int T = in_sizes[0] / HIDDEN;   // 4096

    static float *hid = nullptr, *wct = nullptr, *wqbt = nullptr,
                 *wkvbt = nullptr, *wot = nullptr, *qkva = nullptr,
                 *kvn = nullptr, *kv = nullptr, *q = nullptr, *kpe = nullptr,
                 *vt = nullptr, *at = nullptr;
    static cudaStream_t s1;
    static cudaEvent_t evA, evB;
    if (!hid) {
        cudaGetSymbolAddress((void**)&hid,   g_hid);
        cudaGetSymbolAddress((void**)&wct,   g_wct);
        cudaGetSymbolAddress((void**)&wqbt,  g_wqbt);
        cudaGetSymbolAddress((void**)&wkvbt, g_wkvbt);
        cudaGetSymbolAddress((void**)&wot,   g_wot);
        cudaGetSymbolAddress((void**)&qkva,  g_qkva);
        cudaGetSymbolAddress((void**)&kvn,   g_kvn);
        cudaGetSymbolAddress((void**)&kv,    g_kv);
        cudaGetSymbolAddress((void**)&q,     g_q);
        cudaGetSymbolAddress((void**)&kpe,   g_kpe);
        cudaGetSymbolAddress((void**)&vt,    g_vt);
        cudaGetSymbolAddress((void**)&at,    g_at);
        cudaFuncSetAttribute(mm_nt, cudaFuncAttributeMaxDynamicSharedMemorySize, NT_SMEM_BYTES);
        cudaFuncSetAttribute(flash_attn, cudaFuncAttributeMaxDynamicSharedMemorySize, FL_SMEM_BYTES);
        cudaStreamCreateWithFlags(&s1, cudaStreamNonBlocking);
        cudaEventCreateWithFlags(&evA, cudaEventDisableTiming);
        cudaEventCreateWithFlags(&evB, cudaEventDisableTiming);
    }

    const dim3 thr(256);

    // fused prep
    prep_all<<<PREP_TOTAL, thr>>>(
        (const float4*)hidden, (float4*)hid,
        Wqa, Wkva, Wqb, Wkvb, Wo, wct, wqbt, wkvbt, wot);

    // qkva = hid @ Wc^T
    mm_nt<<<dim3((NC + BN - 1) / BN, T / BM), thr, NT_SMEM_BYTES>>>(
        hid, wct, qkva, T, NC, HIDDEN, HIDDEN, HIDDEN, NC, 1.f, 0);

    // fork: kv path on s1, q path on capture stream
    cudaEventRecord(evA, 0);
    cudaStreamWaitEvent(s1, evA, 0);

    // q path (capture stream)
    rmsnorm_k<<<T, 256>>>(qkva, q_ln, qkva, Q_LORA, NC, NC);
    mm_nt<<<dim3(3072 / BN, T / BM), thr, NT_SMEM_BYTES>>>(
        qkva, wqbt, q, T, 3072, Q_LORA, NC, Q_LORA, 3072, 1.f, 1);

    // kv path (s1)
    rmsnorm_k<<<T, 256, 0, s1>>>(qkva + Q_LORA, kv_ln, kvn, KV_LORA, NC, KV_LORA);
    mm_nt<<<dim3(4096 / BN, T / BM), thr, NT_SMEM_BYTES, s1>>>(
        kvn, wkvbt, kv, T, 4096, KV_LORA, KV_LORA, KV_LORA, 4096, 1.f, 1);
    transpose_v<<<dim3(T / 32, N_HEADS), thr, 0, s1>>>(kv, vt, T);
    cudaEventRecord(evB, s1);

    // join
    cudaStreamWaitEvent(0, evB, 0);

    // rope q in place + kpe
    rope_q_kpe<<<T, 256>>>(q, qkva, kpe, T);
    // fused attention (K from kv + kpe)
    flash_attn<<<dim3(T / 128, N_HEADS), thr, FL_SMEM_BYTES>>>(q, kv, kpe, vt, at, T);
    // out = at @ Wo^T
    mm_nt<<<dim3(HIDDEN / BN, T / BM), thr, NT_SMEM_BYTES>>>(
        at, wot, out, T, HIDDEN, HIDDEN, HIDDEN, HIDDEN, HIDDEN, 1.f, 0);
}